// round 7
// baseline (speedup 1.0000x reference)
#include <cuda_runtime.h>
#include <cstdint>

#define Bn 8
#define Hn 64
#define Wn 64
#define HW 4096
#define KK 9
#define EPSV 1e-4f
#define SA 136              // wn_s row stride (floats): (q*136+g)%32 = q*8+g unique
#define SB 36               // cols_s row stride (floats): (g*36+q)%32 = g*4+q unique

#define WN_FL   (32 * SA)                   // 4352 floats per wn stage
#define COL_FL  (256 * SB)                  // 9216 floats per cols stage
#define ST_FL   (2 * 256 * 8)               // 4096 floats: gather state [slot][px][8]
#define SMEM_FL (2 * WN_FL + 2 * COL_FL + ST_FL)   // 31232 floats = 124928 B

__device__ float g_xt[Bn * HW * 128];       // x transposed [b][hw][c]
__device__ float g_wnt[KK * 128 * 128];     // normalized wn [k][c][o], tf32-rounded

__device__ __forceinline__ float to_tf32(float x) {
    float r; asm("cvt.rna.tf32.f32 %0, %1;" : "=f"(r) : "f"(x)); return r;
}
__device__ __forceinline__ uint32_t smem_u32(const void* p) {
    uint32_t a;
    asm("{ .reg .u64 t; cvta.to.shared.u64 t, %1; cvt.u32.u64 %0, t; }" : "=r"(a) : "l"(p));
    return a;
}
__device__ __forceinline__ void mma_tf32(float* d, const uint32_t* a, const uint32_t* b) {
    asm volatile(
        "mma.sync.aligned.m16n8k8.row.col.f32.tf32.tf32.f32 "
        "{%0,%1,%2,%3}, {%4,%5,%6,%7}, {%8,%9}, {%0,%1,%2,%3};"
        : "+f"(d[0]), "+f"(d[1]), "+f"(d[2]), "+f"(d[3])
        : "r"(a[0]), "r"(a[1]), "r"(a[2]), "r"(a[3]), "r"(b[0]), "r"(b[1]));
}
#define CP_ASYNC16(dst, src) \
    asm volatile("cp.async.ca.shared.global [%0], [%1], 16;" :: "r"(dst), "l"(src) : "memory")
#define CP_COMMIT()  asm volatile("cp.async.commit_group;" ::: "memory")
#define CP_WAIT0()   asm volatile("cp.async.wait_group 0;" ::: "memory")

// ---- kernel 1: prep = transpose x + normalize weights ----
__global__ void prep_kernel(const float* __restrict__ x, const float* __restrict__ w) {
    if (blockIdx.x < 4096) {
        __shared__ float s[32][33];
        int id = blockIdx.x;
        int b = id >> 9, rest = id & 511;
        int c0 = (rest >> 7) * 32, hw0 = (rest & 127) * 32;
        int tx = threadIdx.x & 31, ty = threadIdx.x >> 5;
        #pragma unroll
        for (int p = 0; p < 4; p++)
            s[ty + p * 8][tx] = x[(size_t)(b * 128 + c0 + ty + p * 8) * HW + hw0 + tx];
        __syncthreads();
        #pragma unroll
        for (int p = 0; p < 4; p++)
            g_xt[(size_t)(b * HW + hw0 + ty + p * 8) * 128 + c0 + tx] = s[tx][ty + p * 8];
    } else {
        int k = blockIdx.x - 4096;
        int o = threadIdx.x;
        if (o < 128) {
            float s = 0.f;
            #pragma unroll 8
            for (int c = 0; c < 128; c++) { float v = w[(o * 128 + c) * KK + k]; s += v * v; }
            float inv = 1.0f / (sqrtf(s + 128.0f * EPSV) * 3.0f);
            #pragma unroll 8
            for (int c = 0; c < 128; c++)
                g_wnt[(k * 128 + c) * 128 + o] = to_tf32(w[(o * 128 + c) * KK + k] * inv);
        }
    }
}

// compute bilinear state for pixel px at kernel tap k; write 8 floats to stp[px*8..]
__device__ __forceinline__ void write_state(float* stp, const float* __restrict__ offset,
                                            int b, int k, int px, int ho0) {
    const int gho = ho0 + (px >> 6), gwo = px & 63;
    const int ky = k / 3, kx = k - ky * 3;
    const float offy = __ldg(&offset[(((b * 18) + 2 * k    ) * Hn + gho) * Wn + gwo]);
    const float offx = __ldg(&offset[(((b * 18) + 2 * k + 1) * Hn + gho) * Wn + gwo]);
    const float py  = (float)(gho - 1 + ky) + offy;
    const float pxf = (float)(gwo - 1 + kx) + offx;
    const float y0f = floorf(py), x0f = floorf(pxf);
    const float ly = py - y0f, lx = pxf - x0f;
    const int y0 = (int)y0f, x0 = (int)x0f, y1 = y0 + 1, x1 = x0 + 1;
    float w00 = (1.f - ly) * (1.f - lx), w01 = (1.f - ly) * lx;
    float w10 = ly * (1.f - lx),        w11 = ly * lx;
    if (!((y0 >= 0) & (y0 < Hn) & (x0 >= 0) & (x0 < Wn))) w00 = 0.f;
    if (!((y0 >= 0) & (y0 < Hn) & (x1 >= 0) & (x1 < Wn))) w01 = 0.f;
    if (!((y1 >= 0) & (y1 < Hn) & (x0 >= 0) & (x0 < Wn))) w10 = 0.f;
    if (!((y1 >= 0) & (y1 < Hn) & (x1 >= 0) & (x1 < Wn))) w11 = 0.f;
    const int yc0 = min(max(y0, 0), Hn - 1), yc1 = min(max(y1, 0), Hn - 1);
    const int xc0 = min(max(x0, 0), Wn - 1), xc1 = min(max(x1, 0), Wn - 1);
    float4 s0 = make_float4(w00, w01, w10, w11);
    float4 s1 = make_float4(__int_as_float(yc0 * Wn + xc0), __int_as_float(yc0 * Wn + xc1),
                            __int_as_float(yc1 * Wn + xc0), __int_as_float(yc1 * Wn + xc1));
    *(float4*)&stp[px * 8]     = s0;
    *(float4*)&stp[px * 8 + 4] = s1;
}

// ---- kernel 2: main — pipelined im2col gather + tf32 mma.sync GEMM ----
// grid 128, 512 thr. block = (b, 4 rows): D[128co][256px], 16 warps 32co x 64px
__global__ __launch_bounds__(512, 1)
void deform_main_kernel(const float* __restrict__ offset, float* __restrict__ out) {
    extern __shared__ float sm[];
    float* wnb[2]  = { sm, sm + WN_FL };
    float* colb[2] = { sm + 2 * WN_FL, sm + 2 * WN_FL + COL_FL };
    float* stb[2]  = { sm + 2 * WN_FL + 2 * COL_FL, sm + 2 * WN_FL + 2 * COL_FL + 256 * 8 };
    const uint32_t wnb_u32[2] = { smem_u32(wnb[0]), smem_u32(wnb[1]) };

    const int t = threadIdx.x;
    const int b = blockIdx.x >> 4;
    const int ho0 = (blockIdx.x & 15) * 4;

    // gather mapping: 4 threads/pixel, 2 passes of 128 px; thread reads 8 ch (32B)
    const int gpx0 = t >> 2;          // pass-0 pixel; pass-1 pixel = gpx0+128
    const int j8   = (t & 3) * 8;     // channel sub-range within 32-chunk
    // mma mapping: 16 warps = 4m x 4n
    const int w = t >> 5, lane = t & 31;
    const int m0 = (w & 3) * 32, n0 = (w >> 2) * 64;
    const int g = lane >> 2, q = lane & 3;

    float acc[2][8][4];
    #pragma unroll
    for (int mt = 0; mt < 2; mt++)
        #pragma unroll
        for (int nt = 0; nt < 8; nt++)
            #pragma unroll
            for (int r = 0; r < 4; r++) acc[mt][nt][r] = 0.f;

    const float* xb = g_xt + (size_t)b * HW * 128;

    // ---- prologue ----
    if (!(t & 1)) write_state(stb[0], offset, b, 0, t >> 1, ho0);
    {
        const float* src = g_wnt;   // wn chunk 0
        #pragma unroll
        for (int p = 0; p < 2; p++) {
            int e16 = p * 512 + t;
            int c = e16 >> 5, off = (e16 & 31) * 4;
            CP_ASYNC16(wnb_u32[0] + (uint32_t)(c * SA + off) * 4, src + e16 * 4);
        }
        CP_COMMIT();
    }
    __syncthreads();    // state(k0) visible
    // gather chunk 0 (cc=0) into colb[0]
    #pragma unroll
    for (int p = 0; p < 2; p++) {
        const int px = p * 128 + gpx0;
        float4 sw = *(const float4*)&stb[0][px * 8];
        float4 si = *(const float4*)&stb[0][px * 8 + 4];
        const float* base = xb + j8;
        const float* p00 = base + (size_t)__float_as_int(si.x) * 128;
        const float* p01 = base + (size_t)__float_as_int(si.y) * 128;
        const float* p10 = base + (size_t)__float_as_int(si.z) * 128;
        const float* p11 = base + (size_t)__float_as_int(si.w) * 128;
        #pragma unroll
        for (int hf = 0; hf < 2; hf++) {
            float4 a = *(const float4*)(p00 + hf * 4);
            float4 bb = *(const float4*)(p01 + hf * 4);
            float4 c = *(const float4*)(p10 + hf * 4);
            float4 d = *(const float4*)(p11 + hf * 4);
            float4 v;
            v.x = to_tf32(sw.x * a.x + sw.y * bb.x + sw.z * c.x + sw.w * d.x);
            v.y = to_tf32(sw.x * a.y + sw.y * bb.y + sw.z * c.y + sw.w * d.y);
            v.z = to_tf32(sw.x * a.z + sw.y * bb.z + sw.z * c.z + sw.w * d.z);
            v.w = to_tf32(sw.x * a.w + sw.y * bb.w + sw.z * c.w + sw.w * d.w);
            *(float4*)&colb[0][px * SB + j8 + hf * 4] = v;
        }
    }
    CP_WAIT0();

    // ---- pipelined main loop over 36 chunks ----
    for (int it = 0; it < 36; it++) {
        const int cur = it & 1, nxt = cur ^ 1;
        __syncthreads();

        const bool more = (it < 35);
        if (more) {
            const float* src = g_wnt + (size_t)(it + 1) * 4096;
            #pragma unroll
            for (int p = 0; p < 2; p++) {
                int e16 = p * 512 + t;
                int c = e16 >> 5, off = (e16 & 31) * 4;
                CP_ASYNC16(wnb_u32[nxt] + (uint32_t)(c * SA + off) * 4, src + e16 * 4);
            }
            CP_COMMIT();
        }
        // state for k=(it+2)/4, two chunks ahead of first use
        if ((((it + 2) & 3) == 0) && (it + 2 < 36) && !(t & 1))
            write_state(stb[((it + 2) >> 2) & 1], offset, b, (it + 2) >> 2, t >> 1, ho0);

        const int kn = (it + 1) >> 2, slot = kn & 1, ccn = (it + 1) & 3;
        const float* wnc = wnb[cur];
        const float* colc = colb[cur];
        float* coln = colb[nxt];
        const float* stp = stb[slot];

        // pass-0 corner issue (pixel gpx0, chunk it+1)
        float4 c00a, c00b, c01a, c01b, c10a, c10b, c11a, c11b;
        if (more) {
            float4 si = *(const float4*)&stp[gpx0 * 8 + 4];
            const float* base = xb + ccn * 32 + j8;
            const float* p00 = base + (size_t)__float_as_int(si.x) * 128;
            const float* p01 = base + (size_t)__float_as_int(si.y) * 128;
            const float* p10 = base + (size_t)__float_as_int(si.z) * 128;
            const float* p11 = base + (size_t)__float_as_int(si.w) * 128;
            c00a = *(const float4*)p00;       c00b = *(const float4*)(p00 + 4);
            c01a = *(const float4*)p01;       c01b = *(const float4*)(p01 + 4);
            c10a = *(const float4*)p10;       c10b = *(const float4*)(p10 + 4);
            c11a = *(const float4*)p11;       c11b = *(const float4*)(p11 + 4);
        }

        #pragma unroll
        for (int half = 0; half < 2; half++) {
            // two MMA k-steps
            #pragma unroll
            for (int ss = 0; ss < 2; ss++) {
                const int c8 = (half * 2 + ss) * 8;
                uint32_t af[2][4];
                #pragma unroll
                for (int mt = 0; mt < 2; mt++) {
                    const int row = m0 + mt * 16 + g;
                    af[mt][0] = __float_as_uint(wnc[(c8 + q) * SA + row]);
                    af[mt][1] = __float_as_uint(wnc[(c8 + q) * SA + row + 8]);
                    af[mt][2] = __float_as_uint(wnc[(c8 + q + 4) * SA + row]);
                    af[mt][3] = __float_as_uint(wnc[(c8 + q + 4) * SA + row + 8]);
                }
                uint32_t bf[8][2];
                #pragma unroll
                for (int nt = 0; nt < 8; nt++) {
                    const int px = n0 + nt * 8 + g;
                    bf[nt][0] = __float_as_uint(colc[px * SB + c8 + q]);
                    bf[nt][1] = __float_as_uint(colc[px * SB + c8 + q + 4]);
                }
                #pragma unroll
                for (int mt = 0; mt < 2; mt++)
                    #pragma unroll
                    for (int nt = 0; nt < 8; nt++)
                        mma_tf32(acc[mt][nt], af[mt], bf[nt]);
            }
            // blend the pass issued ~2 k-steps ago; issue next pass
            if (more) {
                const int px = half * 128 + gpx0;
                float4 sw = *(const float4*)&stp[px * 8];
                float4 v;
                v.x = to_tf32(sw.x * c00a.x + sw.y * c01a.x + sw.z * c10a.x + sw.w * c11a.x);
                v.y = to_tf32(sw.x * c00a.y + sw.y * c01a.y + sw.z * c10a.y + sw.w * c11a.y);
                v.z = to_tf32(sw.x * c00a.z + sw.y * c01a.z + sw.z * c10a.z + sw.w * c11a.z);
                v.w = to_tf32(sw.x * c00a.w + sw.y * c01a.w + sw.z * c10a.w + sw.w * c11a.w);
                *(float4*)&coln[px * SB + j8] = v;
                v.x = to_tf32(sw.x * c00b.x + sw.y * c01b.x + sw.z * c10b.x + sw.w * c11b.x);
                v.y = to_tf32(sw.x * c00b.y + sw.y * c01b.y + sw.z * c10b.y + sw.w * c11b.y);
                v.z = to_tf32(sw.x * c00b.z + sw.y * c01b.z + sw.z * c10b.z + sw.w * c11b.z);
                v.w = to_tf32(sw.x * c00b.w + sw.y * c01b.w + sw.z * c10b.w + sw.w * c11b.w);
                *(float4*)&coln[px * SB + j8 + 4] = v;
                if (half == 0) {   // issue pass-1 corners (pixel gpx0+128)
                    float4 si = *(const float4*)&stp[(128 + gpx0) * 8 + 4];
                    const float* base = xb + ccn * 32 + j8;
                    const float* p00 = base + (size_t)__float_as_int(si.x) * 128;
                    const float* p01 = base + (size_t)__float_as_int(si.y) * 128;
                    const float* p10 = base + (size_t)__float_as_int(si.z) * 128;
                    const float* p11 = base + (size_t)__float_as_int(si.w) * 128;
                    c00a = *(const float4*)p00;   c00b = *(const float4*)(p00 + 4);
                    c01a = *(const float4*)p01;   c01b = *(const float4*)(p01 + 4);
                    c10a = *(const float4*)p10;   c10b = *(const float4*)(p10 + 4);
                    c11a = *(const float4*)p11;   c11b = *(const float4*)(p11 + 4);
                }
            }
        }
        if (more) CP_WAIT0();
    }

    // ---- epilogue: out[b][cout][ho][wo] ----
    const int ho = ho0 + (n0 >> 6);
    #pragma unroll
    for (int mt = 0; mt < 2; mt++) {
        const int r0 = m0 + mt * 16 + g;
        #pragma unroll
        for (int nt = 0; nt < 8; nt++) {
            const int wo = nt * 8 + 2 * q;
            float2 v0 = make_float2(acc[mt][nt][0], acc[mt][nt][1]);
            float2 v1 = make_float2(acc[mt][nt][2], acc[mt][nt][3]);
            *(float2*)&out[((size_t)(b * 128 + r0)     * HW) + ho * Wn + wo] = v0;
            *(float2*)&out[((size_t)(b * 128 + r0 + 8) * HW) + ho * Wn + wo] = v1;
        }
    }
}

// ---------------------------------------------------------------------------
extern "C" void kernel_launch(void* const* d_in, const int* in_sizes, int n_in,
                              void* d_out, int out_size) {
    const float* x      = (const float*)d_in[0];   // (8,128,64,64)
    const float* offset = (const float*)d_in[1];   // (8,18,64,64)
    const float* weight = (const float*)d_in[2];   // (128,128,3,3)
    float* out = (float*)d_out;                    // (8,128,64,64)

    cudaFuncSetAttribute(deform_main_kernel,
                         cudaFuncAttributeMaxDynamicSharedMemorySize, SMEM_FL * 4);
    prep_kernel<<<4105, 256>>>(x, weight);
    deform_main_kernel<<<128, 512, SMEM_FL * 4>>>(offset, out);
}

// round 8
// speedup vs baseline: 1.0630x; 1.0630x over previous
#include <cuda_runtime.h>
#include <cstdint>

#define Bn 8
#define Hn 64
#define Wn 64
#define HW 4096
#define KK 9
#define EPSV 1e-4f
#define SA 136              // wn_s row stride: (q*136+g)%32 = q*8+g unique -> conflict-free
#define SB 36               // cols_s row stride: (g*36+q)%32 = g*4+q unique -> conflict-free

#define WN_FL   (32 * SA)                   // 4352 floats per wn stage
#define COL_FL  (128 * SB)                  // 4608 floats per cols stage (128 px)
#define SMEM_FL (2 * (WN_FL + COL_FL))      // 17920 floats = 71680 B per CTA

__device__ float g_xt[Bn * HW * 128];       // x transposed [b][hw][c]
__device__ float g_wnt[KK * 128 * 128];     // normalized wn [k][c][o], tf32-rounded

__device__ __forceinline__ float to_tf32(float x) {
    float r; asm("cvt.rna.tf32.f32 %0, %1;" : "=f"(r) : "f"(x)); return r;
}
__device__ __forceinline__ uint32_t smem_u32(const void* p) {
    uint32_t a;
    asm("{ .reg .u64 t; cvta.to.shared.u64 t, %1; cvt.u32.u64 %0, t; }" : "=r"(a) : "l"(p));
    return a;
}
__device__ __forceinline__ void mma_tf32(float* d, const uint32_t* a, const uint32_t* b) {
    asm volatile(
        "mma.sync.aligned.m16n8k8.row.col.f32.tf32.tf32.f32 "
        "{%0,%1,%2,%3}, {%4,%5,%6,%7}, {%8,%9}, {%0,%1,%2,%3};"
        : "+f"(d[0]), "+f"(d[1]), "+f"(d[2]), "+f"(d[3])
        : "r"(a[0]), "r"(a[1]), "r"(a[2]), "r"(a[3]), "r"(b[0]), "r"(b[1]));
}
#define CP_ASYNC16(dst, src) \
    asm volatile("cp.async.ca.shared.global [%0], [%1], 16;" :: "r"(dst), "l"(src) : "memory")
#define CP_COMMIT()  asm volatile("cp.async.commit_group;" ::: "memory")
#define CP_WAIT0()   asm volatile("cp.async.wait_group 0;" ::: "memory")

// bilinear gather parameters for one (pixel, k)
struct GP {
    const float *p00, *p01, *p10, *p11;
    float w00, w01, w10, w11;
};
__device__ __forceinline__ GP gparams(const float* __restrict__ xb,
                                      const float* __restrict__ offset,
                                      int b, int k, int gho, int gwo) {
    const int ky = k / 3, kx = k - ky * 3;
    const float offy = __ldg(&offset[(((b * 18) + 2 * k    ) * Hn + gho) * Wn + gwo]);
    const float offx = __ldg(&offset[(((b * 18) + 2 * k + 1) * Hn + gho) * Wn + gwo]);
    const float py  = (float)(gho - 1 + ky) + offy;
    const float pxf = (float)(gwo - 1 + kx) + offx;
    const float y0f = floorf(py), x0f = floorf(pxf);
    const float ly = py - y0f, lx = pxf - x0f;
    const int y0 = (int)y0f, x0 = (int)x0f, y1 = y0 + 1, x1 = x0 + 1;
    GP g;
    g.w00 = (1.f - ly) * (1.f - lx); g.w01 = (1.f - ly) * lx;
    g.w10 = ly * (1.f - lx);         g.w11 = ly * lx;
    if (!((y0 >= 0) & (y0 < Hn) & (x0 >= 0) & (x0 < Wn))) g.w00 = 0.f;
    if (!((y0 >= 0) & (y0 < Hn) & (x1 >= 0) & (x1 < Wn))) g.w01 = 0.f;
    if (!((y1 >= 0) & (y1 < Hn) & (x0 >= 0) & (x0 < Wn))) g.w10 = 0.f;
    if (!((y1 >= 0) & (y1 < Hn) & (x1 >= 0) & (x1 < Wn))) g.w11 = 0.f;
    const int yc0 = min(max(y0, 0), Hn - 1), yc1 = min(max(y1, 0), Hn - 1);
    const int xc0 = min(max(x0, 0), Wn - 1), xc1 = min(max(x1, 0), Wn - 1);
    g.p00 = xb + (size_t)(yc0 * Wn + xc0) * 128;
    g.p01 = xb + (size_t)(yc0 * Wn + xc1) * 128;
    g.p10 = xb + (size_t)(yc1 * Wn + xc0) * 128;
    g.p11 = xb + (size_t)(yc1 * Wn + xc1) * 128;
    return g;
}

// ---- kernel 1: prep = transpose x + normalize weights (single launch) ----
__global__ void prep_kernel(const float* __restrict__ x, const float* __restrict__ w) {
    if (blockIdx.x < 4096) {
        __shared__ float s[32][33];
        int id = blockIdx.x;
        int b = id >> 9, rest = id & 511;
        int c0 = (rest >> 7) * 32, hw0 = (rest & 127) * 32;
        int tx = threadIdx.x & 31, ty = threadIdx.x >> 5;
        #pragma unroll
        for (int p = 0; p < 4; p++)
            s[ty + p * 8][tx] = x[(size_t)(b * 128 + c0 + ty + p * 8) * HW + hw0 + tx];
        __syncthreads();
        #pragma unroll
        for (int p = 0; p < 4; p++)
            g_xt[(size_t)(b * HW + hw0 + ty + p * 8) * 128 + c0 + tx] = s[tx][ty + p * 8];
    } else {
        int k = blockIdx.x - 4096;
        int o = threadIdx.x;
        if (o < 128) {
            float s = 0.f;
            #pragma unroll 8
            for (int c = 0; c < 128; c++) { float v = w[(o * 128 + c) * KK + k]; s += v * v; }
            float inv = 1.0f / (sqrtf(s + 128.0f * EPSV) * 3.0f);
            #pragma unroll 8
            for (int c = 0; c < 128; c++)
                g_wnt[(k * 128 + c) * 128 + o] = to_tf32(w[(o * 128 + c) * KK + k] * inv);
        }
    }
}

// ---- kernel 2: main — pipelined im2col gather + tf32 mma.sync GEMM ----
// grid 256, 256 thr, 2 CTAs/SM. block = (b, 2 rows): D[128co][128px],
// 8 warps = 4m x 2n, each 32co x 64px.
__global__ __launch_bounds__(256, 2)
void deform_main_kernel(const float* __restrict__ offset, float* __restrict__ out) {
    extern __shared__ float sm[];
    float* wnb[2]  = { sm, sm + WN_FL };
    float* colb[2] = { sm + 2 * WN_FL, sm + 2 * WN_FL + COL_FL };
    const uint32_t wnb_u32[2] = { smem_u32(wnb[0]), smem_u32(wnb[1]) };

    const int t = threadIdx.x;
    const int b = blockIdx.x >> 5;
    const int ho0 = (blockIdx.x & 31) * 2;

    // gather mapping: 2 threads per pixel (128 px), 16 channels each
    const int gpx = t >> 1, h = t & 1;
    const int gho = ho0 + (gpx >> 6), gwo = gpx & 63;
    // mma mapping: 8 warps = 4m x 2n
    const int w = t >> 5, lane = t & 31;
    const int m0 = (w & 3) * 32, n0 = (w >> 2) * 64;
    const int g = lane >> 2, q = lane & 3;

    float acc[2][8][4];
    #pragma unroll
    for (int mt = 0; mt < 2; mt++)
        #pragma unroll
        for (int nt = 0; nt < 8; nt++)
            #pragma unroll
            for (int r = 0; r < 4; r++) acc[mt][nt][r] = 0.f;

    const float* xb = g_xt + (size_t)b * HW * 128;

    // ---- prologue: gather chunk 0 into colb[0], cp.async wn chunk 0 ----
    GP gp = gparams(xb, offset, b, 0, gho, gwo);
    {
        #pragma unroll
        for (int sub = 0; sub < 4; sub++) {
            const int co = h * 16 + sub * 4;
            float4 a = *(const float4*)(gp.p00 + co);
            float4 bb = *(const float4*)(gp.p01 + co);
            float4 c = *(const float4*)(gp.p10 + co);
            float4 d = *(const float4*)(gp.p11 + co);
            float4 v;
            v.x = to_tf32(gp.w00 * a.x + gp.w01 * bb.x + gp.w10 * c.x + gp.w11 * d.x);
            v.y = to_tf32(gp.w00 * a.y + gp.w01 * bb.y + gp.w10 * c.y + gp.w11 * d.y);
            v.z = to_tf32(gp.w00 * a.z + gp.w01 * bb.z + gp.w10 * c.z + gp.w11 * d.z);
            v.w = to_tf32(gp.w00 * a.w + gp.w01 * bb.w + gp.w10 * c.w + gp.w11 * d.w);
            *(float4*)&colb[0][gpx * SB + co] = v;
        }
        const float* src = g_wnt;   // chunk 0
        #pragma unroll
        for (int p = 0; p < 4; p++) {
            int e16 = p * 256 + t;
            int c = e16 >> 5, off = (e16 & 31) * 4;
            CP_ASYNC16(wnb_u32[0] + (uint32_t)(c * SA + off) * 4, src + e16 * 4);
        }
        CP_COMMIT();
        CP_WAIT0();
    }

    // ---- pipelined main loop over 36 chunks ----
    for (int it = 0; it < 36; it++) {
        const int cur = it & 1, nxt = cur ^ 1;
        __syncthreads();     // colb[cur] STS visible; all warps done with [nxt] buffers

        const bool more = (it + 1 < 36);
        if (more) {
            // prefetch wn chunk it+1
            const float* src = g_wnt + (size_t)(it + 1) * 4096;
            #pragma unroll
            for (int p = 0; p < 4; p++) {
                int e16 = p * 256 + t;
                int c = e16 >> 5, off = (e16 & 31) * 4;
                CP_ASYNC16(wnb_u32[nxt] + (uint32_t)(c * SA + off) * 4, src + e16 * 4);
            }
            CP_COMMIT();
            if (((it + 1) & 3) == 0)
                gp = gparams(xb, offset, b, (it + 1) >> 2, gho, gwo);
        }
        const int ccn = (it + 1) & 3;           // c-chunk index of next
        const float* wnc = wnb[cur];
        const float* colc = colb[cur];
        float* coln = colb[nxt];

        #pragma unroll
        for (int sub = 0; sub < 4; sub++) {
            // issue next-chunk corner loads for this channel-quad (hidden under MMA)
            float4 a, bb, c, d;
            if (more) {
                const int co = ccn * 32 + h * 16 + sub * 4;   // global channel
                a  = *(const float4*)(gp.p00 + co);
                bb = *(const float4*)(gp.p01 + co);
                c  = *(const float4*)(gp.p10 + co);
                d  = *(const float4*)(gp.p11 + co);
            }
            // MMA k-step
            const int c8 = sub * 8;
            uint32_t af[2][4];
            #pragma unroll
            for (int mt = 0; mt < 2; mt++) {
                const int row = m0 + mt * 16 + g;
                af[mt][0] = __float_as_uint(wnc[(c8 + q) * SA + row]);
                af[mt][1] = __float_as_uint(wnc[(c8 + q) * SA + row + 8]);
                af[mt][2] = __float_as_uint(wnc[(c8 + q + 4) * SA + row]);
                af[mt][3] = __float_as_uint(wnc[(c8 + q + 4) * SA + row + 8]);
            }
            uint32_t bf[8][2];
            #pragma unroll
            for (int nt = 0; nt < 8; nt++) {
                const int px = n0 + nt * 8 + g;
                bf[nt][0] = __float_as_uint(colc[px * SB + c8 + q]);
                bf[nt][1] = __float_as_uint(colc[px * SB + c8 + q + 4]);
            }
            #pragma unroll
            for (int mt = 0; mt < 2; mt++)
                #pragma unroll
                for (int nt = 0; nt < 8; nt++)
                    mma_tf32(acc[mt][nt], af[mt], bf[nt]);

            // blend + store next-chunk quad (LOCAL channel index in smem)
            if (more) {
                float4 v;
                v.x = to_tf32(gp.w00 * a.x + gp.w01 * bb.x + gp.w10 * c.x + gp.w11 * d.x);
                v.y = to_tf32(gp.w00 * a.y + gp.w01 * bb.y + gp.w10 * c.y + gp.w11 * d.y);
                v.z = to_tf32(gp.w00 * a.z + gp.w01 * bb.z + gp.w10 * c.z + gp.w11 * d.z);
                v.w = to_tf32(gp.w00 * a.w + gp.w01 * bb.w + gp.w10 * c.w + gp.w11 * d.w);
                *(float4*)&coln[gpx * SB + h * 16 + sub * 4] = v;
            }
        }
        if (more) CP_WAIT0();
    }

    // ---- epilogue: out[b][cout][ho][wo]; warp n-half selects output row ----
    const int ho = ho0 + (n0 >> 6);
    #pragma unroll
    for (int mt = 0; mt < 2; mt++) {
        const int r0 = m0 + mt * 16 + g;
        #pragma unroll
        for (int nt = 0; nt < 8; nt++) {
            const int wo = nt * 8 + 2 * q;
            float2 v0 = make_float2(acc[mt][nt][0], acc[mt][nt][1]);
            float2 v1 = make_float2(acc[mt][nt][2], acc[mt][nt][3]);
            *(float2*)&out[((size_t)(b * 128 + r0)     * HW) + ho * Wn + wo] = v0;
            *(float2*)&out[((size_t)(b * 128 + r0 + 8) * HW) + ho * Wn + wo] = v1;
        }
    }
}

// ---------------------------------------------------------------------------
extern "C" void kernel_launch(void* const* d_in, const int* in_sizes, int n_in,
                              void* d_out, int out_size) {
    const float* x      = (const float*)d_in[0];   // (8,128,64,64)
    const float* offset = (const float*)d_in[1];   // (8,18,64,64)
    const float* weight = (const float*)d_in[2];   // (128,128,3,3)
    float* out = (float*)d_out;                    // (8,128,64,64)

    cudaFuncSetAttribute(deform_main_kernel,
                         cudaFuncAttributeMaxDynamicSharedMemorySize, SMEM_FL * 4);
    prep_kernel<<<4105, 256>>>(x, weight);
    deform_main_kernel<<<256, 256, SMEM_FL * 4>>>(offset, out);
}